// round 15
// baseline (speedup 1.0000x reference)
#include <cuda_runtime.h>
#include <cuda_fp16.h>
#include <cstdint>

#define D 128
#define NMAX 100000
#define EMAX 3200000
#define FULL 0xffffffffu

// Scratch in device globals (no runtime allocation).
__device__ float  g_h0[NMAX * D];
__device__ __half g_h1h[NMAX * D];      // h1 in fp16 (agg gather payload)
__device__ float  g_aself[NMAX];
__device__ float  g_aneigh[NMAX];
__device__ int    g_deg[NMAX + 4];
__device__ int    g_off[NMAX + 1];
__device__ int    g_cur[NMAX];
__device__ int2   g_epack[EMAX];        // {col, f32 bits of a_neigh[col]}
__device__ int    g_bsum[512];
__device__ int    g_boff[512];

// ---------------------------------------------------------------------------
// Tensor-core GEMM pass, fp16 mma.sync m16n8k16 (fp32 accumulate), ldmatrix.
// Launched twice: cb=1 (W1 -> h1 fp16 + a_neigh) FIRST, then cb=0 (W0 -> h0
// fp32 + a_self). The cb=1-first order lets scatter (needs a_neigh) overlap
// the cb=0 launch on a side stream.
// CTA: 256 thr (8 warps: 4 along M x 2 along N), tile 128 rows x 128 cols.
// smem ~69.5 KB -> 2 CTAs/SM.
// ---------------------------------------------------------------------------
#define HSTRIDE 136
#define TILE_HALVES (128 * HSTRIDE)
#define GEMM_SMEM (2 * TILE_HALVES * 2 + 3 * 128 * 4)

__device__ __forceinline__ void mma_f16(float* c, const uint32_t* a,
                                        uint32_t b0, uint32_t b1)
{
    asm volatile(
        "mma.sync.aligned.m16n8k16.row.col.f32.f16.f16.f32 "
        "{%0,%1,%2,%3}, {%4,%5,%6,%7}, {%8,%9}, {%0,%1,%2,%3};"
        : "+f"(c[0]), "+f"(c[1]), "+f"(c[2]), "+f"(c[3])
        : "r"(a[0]), "r"(a[1]), "r"(a[2]), "r"(a[3]), "r"(b0), "r"(b1));
}

__device__ __forceinline__ void ldsm_x4(uint32_t* r, uint32_t addr)
{
    asm volatile(
        "ldmatrix.sync.aligned.m8n8.x4.shared.b16 {%0,%1,%2,%3}, [%4];"
        : "=r"(r[0]), "=r"(r[1]), "=r"(r[2]), "=r"(r[3])
        : "r"(addr));
}

__global__ __launch_bounds__(256, 2) void gemm_kernel(
    const float* __restrict__ x,
    const float* __restrict__ W, const float* __restrict__ bv,
    const float* __restrict__ attp, int N, int cb)
{
    extern __shared__ __half smh[];
    __half* xs = smh;                     // [128][HSTRIDE]
    __half* ws = smh + TILE_HALVES;       // [128][HSTRIDE]
    float* rowsum = (float*)(smh + 2 * TILE_HALVES);  // [128]
    float* sbias  = rowsum + 128;                     // [128]
    float* satt   = sbias + 128;                      // [128]

    const int tid  = threadIdx.x;
    const int row0 = blockIdx.x * 128;

    if (tid < 128) {
        rowsum[tid] = 0.0f;
        sbias[tid]  = bv[tid];
        satt[tid]   = attp[tid];
    }

    // Stage W and x tiles as fp16: float4 loads -> 2x half2 stores.
    for (int i = tid; i < 128 * 32; i += 256) {
        int r = i >> 5, c4 = (i & 31) * 4;
        float4 wv = *(const float4*)(W + r * 128 + c4);
        *(__half2*)(ws + r * HSTRIDE + c4)     = __floats2half2_rn(wv.x, wv.y);
        *(__half2*)(ws + r * HSTRIDE + c4 + 2) = __floats2half2_rn(wv.z, wv.w);
        int gr = row0 + r;
        float4 xv = (gr < N) ? *(const float4*)(x + (size_t)gr * 128 + c4)
                             : make_float4(0.f, 0.f, 0.f, 0.f);
        *(__half2*)(xs + r * HSTRIDE + c4)     = __floats2half2_rn(xv.x, xv.y);
        *(__half2*)(xs + r * HSTRIDE + c4 + 2) = __floats2half2_rn(xv.z, xv.w);
    }
    __syncthreads();

    const int lane = tid & 31, wid = tid >> 5;
    const int gid  = lane >> 2, tg = lane & 3;
    const int mrow = (wid >> 1) * 32;   // 0,32,64,96
    const int ncol = (wid & 1) * 64;    // 0,64

    // ldmatrix base addresses.
    uint32_t aAddr0, aAddr1, bAddr[4];
    {
        int rowA = mrow + (lane & 7) + ((lane >> 3) & 1) * 8;
        int kA   = ((lane >> 4) & 1) * 8;
        aAddr0 = (uint32_t)__cvta_generic_to_shared(xs + rowA * HSTRIDE + kA);
        aAddr1 = (uint32_t)__cvta_generic_to_shared(xs + (rowA + 16) * HSTRIDE + kA);
        int nB = (lane & 7) + ((lane >> 4) & 1) * 8;
        int kB = ((lane >> 3) & 1) * 8;
#pragma unroll
        for (int ntp = 0; ntp < 4; ntp++)
            bAddr[ntp] = (uint32_t)__cvta_generic_to_shared(
                ws + (ncol + ntp * 16 + nB) * HSTRIDE + kB);
    }

    float acc[2][8][4];
#pragma unroll
    for (int mt = 0; mt < 2; mt++)
#pragma unroll
        for (int nt = 0; nt < 8; nt++)
#pragma unroll
            for (int q = 0; q < 4; q++) acc[mt][nt][q] = 0.0f;

#pragma unroll
    for (int ks = 0; ks < 8; ks++) {
        uint32_t a[2][4];
        ldsm_x4(a[0], aAddr0);
        ldsm_x4(a[1], aAddr1);
        uint32_t b[4][4];
#pragma unroll
        for (int ntp = 0; ntp < 4; ntp++)
            ldsm_x4(b[ntp], bAddr[ntp]);

#pragma unroll
        for (int nt = 0; nt < 8; nt++) {
            uint32_t bq0 = b[nt >> 1][(nt & 1) * 2];
            uint32_t bq1 = b[nt >> 1][(nt & 1) * 2 + 1];
#pragma unroll
            for (int mt = 0; mt < 2; mt++)
                mma_f16(acc[mt][nt], a[mt], bq0, bq1);
        }
        aAddr0 += 32; aAddr1 += 32;
#pragma unroll
        for (int ntp = 0; ntp < 4; ntp++) bAddr[ntp] += 32;
    }

    // Epilogue: bias + relu, store h (fp32 h0 / fp16 h1), attention dots.
    float pr[2][2] = {{0.f, 0.f}, {0.f, 0.f}};
#pragma unroll
    for (int mt = 0; mt < 2; mt++) {
        int rbase = row0 + mrow + mt * 16;
#pragma unroll
        for (int nt = 0; nt < 8; nt++) {
            int n = ncol + nt * 8 + 2 * tg;
            float bia0 = sbias[n], bia1 = sbias[n + 1];
            float at0  = satt[n],  at1  = satt[n + 1];
            float v00 = fmaxf(acc[mt][nt][0] + bia0, 0.0f);
            float v01 = fmaxf(acc[mt][nt][1] + bia1, 0.0f);
            float v10 = fmaxf(acc[mt][nt][2] + bia0, 0.0f);
            float v11 = fmaxf(acc[mt][nt][3] + bia1, 0.0f);
            int r0r = rbase + gid, r1r = rbase + gid + 8;
            if (cb == 0) {
                if (r0r < N) *(float2*)(g_h0 + (size_t)r0r * 128 + n) = make_float2(v00, v01);
                if (r1r < N) *(float2*)(g_h0 + (size_t)r1r * 128 + n) = make_float2(v10, v11);
            } else {
                if (r0r < N) *(__half2*)(g_h1h + (size_t)r0r * 128 + n) =
                    __floats2half2_rn(v00, v01);
                if (r1r < N) *(__half2*)(g_h1h + (size_t)r1r * 128 + n) =
                    __floats2half2_rn(v10, v11);
            }
            pr[mt][0] += v00 * at0 + v01 * at1;
            pr[mt][1] += v10 * at0 + v11 * at1;
        }
    }
#pragma unroll
    for (int mt = 0; mt < 2; mt++)
#pragma unroll
        for (int h = 0; h < 2; h++) {
            float p = pr[mt][h];
            p += __shfl_xor_sync(FULL, p, 1);
            p += __shfl_xor_sync(FULL, p, 2);
            pr[mt][h] = p;
        }
    if (tg == 0) {
        atomicAdd(&rowsum[mrow + gid     ], pr[0][0]);
        atomicAdd(&rowsum[mrow + gid + 8 ], pr[0][1]);
        atomicAdd(&rowsum[mrow + gid + 16], pr[1][0]);
        atomicAdd(&rowsum[mrow + gid + 24], pr[1][1]);
    }
    __syncthreads();
    if (tid < 128) {
        int gr = row0 + tid;
        if (gr < N) {
            float p = rowsum[tid];
            p = (p > 0.0f) ? p : 0.2f * p;
            if (cb) g_aneigh[gr] = p;
            else    g_aself[gr]  = p;
        }
    }
}

// ---------------------------------------------------------------------------
// Side-stream chain: zero_deg -> hist -> 3-kernel scan -> (after gemm1) scatter
// ---------------------------------------------------------------------------
__global__ __launch_bounds__(256) void zero_deg_kernel(int N)
{
    int i = blockIdx.x * 256 + threadIdx.x;
    if (i < N + 4) g_deg[i] = 0;
}

__global__ __launch_bounds__(256) void hist_kernel(const int* __restrict__ row, int E)
{
    int i0 = (blockIdx.x * 256 + threadIdx.x) * 4;
    if (i0 + 3 < E) {
        int4 r4 = *(const int4*)(row + i0);
        atomicAdd(&g_deg[r4.x], 1);
        atomicAdd(&g_deg[r4.y], 1);
        atomicAdd(&g_deg[r4.z], 1);
        atomicAdd(&g_deg[r4.w], 1);
    } else {
        for (int i = i0; i < E; i++) atomicAdd(&g_deg[row[i]], 1);
    }
}

__global__ __launch_bounds__(512) void scan1_kernel(int N)
{
    int t = threadIdx.x, b = blockIdx.x;
    int i = b * 512 + t;
    int lane = t & 31, w = t >> 5;
    int v = (i < N) ? g_deg[i] : 0;
#pragma unroll
    for (int o = 1; o < 32; o <<= 1) {
        int n = __shfl_up_sync(FULL, v, o);
        if (lane >= o) v += n;
    }
    __shared__ int ws[16];
    if (lane == 31) ws[w] = v;
    __syncthreads();
    if (w == 0) {
        int s = (lane < 16) ? ws[lane] : 0;
#pragma unroll
        for (int o = 1; o < 16; o <<= 1) {
            int n = __shfl_up_sync(FULL, s, o);
            if (lane >= o) s += n;
        }
        if (lane < 16) ws[lane] = s;
    }
    __syncthreads();
    if (w > 0) v += ws[w - 1];
    if (i < N) g_off[i + 1] = v;
    if (t == 511) g_bsum[b] = v;
}

__global__ __launch_bounds__(512) void scan2_kernel(int nb)
{
    int t = threadIdx.x;
    int lane = t & 31, w = t >> 5;
    int orig = (t < nb) ? g_bsum[t] : 0;
    int v = orig;
#pragma unroll
    for (int o = 1; o < 32; o <<= 1) {
        int n = __shfl_up_sync(FULL, v, o);
        if (lane >= o) v += n;
    }
    __shared__ int ws[16];
    if (lane == 31) ws[w] = v;
    __syncthreads();
    if (w == 0) {
        int s = (lane < 16) ? ws[lane] : 0;
#pragma unroll
        for (int o = 1; o < 16; o <<= 1) {
            int n = __shfl_up_sync(FULL, s, o);
            if (lane >= o) s += n;
        }
        if (lane < 16) ws[lane] = s;
    }
    __syncthreads();
    if (w > 0) v += ws[w - 1];
    if (t < nb) g_boff[t] = v - orig;   // exclusive
}

__global__ __launch_bounds__(512) void scan3_kernel(int N)
{
    int t = threadIdx.x, b = blockIdx.x;
    int i = b * 512 + t;
    if (i < N) {
        int val = g_off[i + 1] + g_boff[b];
        g_off[i + 1] = val;
        g_cur[i] = val - g_deg[i];
    }
    if (i == 0) g_off[0] = 0;
}

__global__ __launch_bounds__(256) void scatter_kernel(
    const int* __restrict__ row, const int* __restrict__ col, int E)
{
    int i0 = (blockIdx.x * 256 + threadIdx.x) * 4;
    if (i0 + 3 < E) {
        int4 r4 = *(const int4*)(row + i0);
        int4 c4 = *(const int4*)(col + i0);
        float a0 = g_aneigh[c4.x], a1 = g_aneigh[c4.y];
        float a2 = g_aneigh[c4.z], a3 = g_aneigh[c4.w];
        int p0 = atomicAdd(&g_cur[r4.x], 1);
        int p1 = atomicAdd(&g_cur[r4.y], 1);
        int p2 = atomicAdd(&g_cur[r4.z], 1);
        int p3 = atomicAdd(&g_cur[r4.w], 1);
        g_epack[p0] = make_int2(c4.x, __float_as_int(a0));
        g_epack[p1] = make_int2(c4.y, __float_as_int(a1));
        g_epack[p2] = make_int2(c4.z, __float_as_int(a2));
        g_epack[p3] = make_int2(c4.w, __float_as_int(a3));
    } else {
        for (int i = i0; i < E; i++) {
            int c = col[i];
            int pos = atomicAdd(&g_cur[row[i]], 1);
            g_epack[pos] = make_int2(c, __float_as_int(g_aneigh[c]));
        }
    }
}

// ---------------------------------------------------------------------------
// Aggregate + fused epilogue: one warp per node (gather, no atomics).
//   agg = sum_{(r,c)} (a_self[r]+a_neigh[c]) * h1[c]   (h1 fp16, e pre-packed)
//   out[r] = norm(h0[r],s0,o0) + norm(agg,s1,o1)
// ---------------------------------------------------------------------------
__global__ __launch_bounds__(256) void agg_kernel(
    const float* __restrict__ scale0, const float* __restrict__ offset0,
    const float* __restrict__ scale1, const float* __restrict__ offset1,
    float* __restrict__ out, int N)
{
    int gw = (blockIdx.x * blockDim.x + threadIdx.x) >> 5;
    int lane = threadIdx.x & 31;
    if (gw >= N) return;

    const int start = g_off[gw];
    const int end   = g_off[gw + 1];
    const float a_r = g_aself[gw];

    float4 acc = make_float4(0.f, 0.f, 0.f, 0.f);

    for (int base = start; base < end; base += 32) {
        int idx = base + lane;
        int2 p = (idx < end) ? g_epack[idx] : make_int2(0, 0);
        int   c = p.x;
        float e = a_r + __int_as_float(p.y);
        int cnt = min(32, end - base);
        int j = 0;
        for (; j + 4 <= cnt; j += 4) {
#pragma unroll
            for (int u = 0; u < 4; u++) {
                int   cj = __shfl_sync(FULL, c, j + u);
                float ej = __shfl_sync(FULL, e, j + u);
                uint2 hp = ((const uint2*)(g_h1h + (size_t)cj * 128))[lane];
                float2 lo = __half22float2(*(__half2*)&hp.x);
                float2 hi = __half22float2(*(__half2*)&hp.y);
                acc.x = fmaf(ej, lo.x, acc.x);
                acc.y = fmaf(ej, lo.y, acc.y);
                acc.z = fmaf(ej, hi.x, acc.z);
                acc.w = fmaf(ej, hi.y, acc.w);
            }
        }
        for (; j < cnt; j++) {
            int   cj = __shfl_sync(FULL, c, j);
            float ej = __shfl_sync(FULL, e, j);
            uint2 hp = ((const uint2*)(g_h1h + (size_t)cj * 128))[lane];
            float2 lo = __half22float2(*(__half2*)&hp.x);
            float2 hi = __half22float2(*(__half2*)&hp.y);
            acc.x = fmaf(ej, lo.x, acc.x);
            acc.y = fmaf(ej, lo.y, acc.y);
            acc.z = fmaf(ej, hi.x, acc.z);
            acc.w = fmaf(ej, hi.y, acc.w);
        }
    }

    const float4 h0v = ((const float4*)(g_h0 + (size_t)gw * 128))[lane];

    float s0 = h0v.x + h0v.y + h0v.z + h0v.w;
    float q0 = h0v.x * h0v.x + h0v.y * h0v.y + h0v.z * h0v.z + h0v.w * h0v.w;
    float s1 = acc.x + acc.y + acc.z + acc.w;
    float q1 = acc.x * acc.x + acc.y * acc.y + acc.z * acc.z + acc.w * acc.w;

#pragma unroll
    for (int o = 16; o > 0; o >>= 1) {
        s0 += __shfl_xor_sync(FULL, s0, o);
        q0 += __shfl_xor_sync(FULL, q0, o);
        s1 += __shfl_xor_sync(FULL, s1, o);
        q1 += __shfl_xor_sync(FULL, q1, o);
    }

    const float m0 = s0 * (1.0f / 128.0f);
    const float i0 = rsqrtf(q0 * (1.0f / 128.0f) - m0 * m0 + 1e-9f);
    const float m1 = s1 * (1.0f / 128.0f);
    const float i1 = rsqrtf(q1 * (1.0f / 128.0f) - m1 * m1 + 1e-9f);

    const float4 sc0 = ((const float4*)scale0)[lane];
    const float4 of0 = ((const float4*)offset0)[lane];
    const float4 sc1 = ((const float4*)scale1)[lane];
    const float4 of1 = ((const float4*)offset1)[lane];

    float4 o4;
    o4.x = (h0v.x - m0) * sc0.x * i0 + of0.x + (acc.x - m1) * sc1.x * i1 + of1.x;
    o4.y = (h0v.y - m0) * sc0.y * i0 + of0.y + (acc.y - m1) * sc1.y * i1 + of1.y;
    o4.z = (h0v.z - m0) * sc0.z * i0 + of0.z + (acc.z - m1) * sc1.z * i1 + of1.z;
    o4.w = (h0v.w - m0) * sc0.w * i0 + of0.w + (acc.w - m1) * sc1.w * i1 + of1.w;
    ((float4*)(out + (size_t)gw * 128))[lane] = o4;
}

// ---------------------------------------------------------------------------
extern "C" void kernel_launch(void* const* d_in, const int* in_sizes, int n_in,
                              void* d_out, int out_size)
{
    const float* x       = (const float*)d_in[0];
    const int*   row     = (const int*)  d_in[1];
    const int*   col     = (const int*)  d_in[2];
    const float* W0      = (const float*)d_in[3];
    const float* b0      = (const float*)d_in[4];
    const float* W1      = (const float*)d_in[5];
    const float* b1      = (const float*)d_in[6];
    const float* att     = (const float*)d_in[7];
    const float* scale0  = (const float*)d_in[8];
    const float* offset0 = (const float*)d_in[9];
    const float* scale1  = (const float*)d_in[10];
    const float* offset1 = (const float*)d_in[11];
    float* out = (float*)d_out;

    const int N = in_sizes[0] / D;
    const int E = in_sizes[1];
    const int nb = (N + 511) / 512;

    // One-time host-side resources (created on the uncaptured correctness call).
    static cudaStream_t s_side = nullptr;
    static cudaEvent_t  s_evFork = nullptr, s_evG1 = nullptr, s_evJoin = nullptr;
    if (!s_side) {
        cudaStreamCreateWithFlags(&s_side, cudaStreamNonBlocking);
        cudaEventCreateWithFlags(&s_evFork, cudaEventDisableTiming);
        cudaEventCreateWithFlags(&s_evG1,   cudaEventDisableTiming);
        cudaEventCreateWithFlags(&s_evJoin, cudaEventDisableTiming);
        cudaFuncSetAttribute(gemm_kernel,
                             cudaFuncAttributeMaxDynamicSharedMemorySize, GEMM_SMEM);
    }

    const int ggrid = (N + 127) / 128;

    // Fork: side stream builds the CSR skeleton while stream 0 runs gemm(cb=1).
    cudaEventRecord(s_evFork, 0);
    cudaStreamWaitEvent(s_side, s_evFork, 0);

    zero_deg_kernel<<<(N + 4 + 255) / 256, 256, 0, s_side>>>(N);
    hist_kernel<<<(E / 4 + 255) / 256, 256, 0, s_side>>>(row, E);
    scan1_kernel<<<nb, 512, 0, s_side>>>(N);
    scan2_kernel<<<1, 512, 0, s_side>>>(nb);
    scan3_kernel<<<nb, 512, 0, s_side>>>(N);

    // gemm pass 1: h1 (fp16) + a_neigh -- scatter's data dependency.
    gemm_kernel<<<ggrid, 256, GEMM_SMEM>>>(x, W1, b1, att + 128, N, 1);
    cudaEventRecord(s_evG1, 0);

    // Side: scatter overlaps gemm pass 0 on the main stream.
    cudaStreamWaitEvent(s_side, s_evG1, 0);
    scatter_kernel<<<(E / 4 + 255) / 256, 256, 0, s_side>>>(row, col, E);
    cudaEventRecord(s_evJoin, s_side);

    // gemm pass 0: h0 (fp32) + a_self.
    gemm_kernel<<<ggrid, 256, GEMM_SMEM>>>(x, W0, b0, att, N, 0);

    // Join: agg needs h0/a_self (main) + epack (side).
    cudaStreamWaitEvent(0, s_evJoin, 0);
    agg_kernel<<<(N * 32 + 255) / 256, 256>>>(scale0, offset0, scale1, offset1, out, N);
}

// round 16
// speedup vs baseline: 1.1004x; 1.1004x over previous
#include <cuda_runtime.h>
#include <cuda_fp16.h>
#include <cstdint>

#define D 128
#define NMAX 100000
#define EMAX 3200000
#define FULL 0xffffffffu

// Scratch in device globals (no runtime allocation).
__device__ __half g_h0h[NMAX * D];      // h0 in fp16 (norm stream payload)
__device__ __half g_h1h[NMAX * D];      // h1 in fp16 (agg gather payload)
__device__ float  g_aself[NMAX];
__device__ float  g_aneigh[NMAX];
__device__ int    g_deg[NMAX + 4];
__device__ int    g_off[NMAX + 1];
__device__ int    g_cur[NMAX];
__device__ int2   g_epack[EMAX];        // {col, f32 bits of a_neigh[col]}
__device__ int    g_bsum[512];
__device__ int    g_boff[512];

// ---------------------------------------------------------------------------
// Tensor-core GEMM, fp16 mma.sync m16n8k16 (fp32 accumulate), ldmatrix loads.
// MERGED: one grid (ceil(N/128)); each CTA stages its x tile ONCE, then loops
// cb=0 (W0 -> h0 fp16 + a_self) and cb=1 (W1 -> h1 fp16 + a_neigh), restaging
// only the 32 KB weight tile per pass.
// CTA: 256 thr (8 warps: 4 along M x 2 along N), tile 128 rows x 128 cols.
// smem ~69.6 KB -> 2 CTAs/SM.
// ---------------------------------------------------------------------------
#define HSTRIDE 136
#define TILE_HALVES (128 * HSTRIDE)
#define GEMM_SMEM (2 * TILE_HALVES * 2 + (128 + 256 + 256) * 4)

__device__ __forceinline__ void mma_f16(float* c, const uint32_t* a,
                                        uint32_t b0, uint32_t b1)
{
    asm volatile(
        "mma.sync.aligned.m16n8k16.row.col.f32.f16.f16.f32 "
        "{%0,%1,%2,%3}, {%4,%5,%6,%7}, {%8,%9}, {%0,%1,%2,%3};"
        : "+f"(c[0]), "+f"(c[1]), "+f"(c[2]), "+f"(c[3])
        : "r"(a[0]), "r"(a[1]), "r"(a[2]), "r"(a[3]), "r"(b0), "r"(b1));
}

__device__ __forceinline__ void ldsm_x4(uint32_t* r, uint32_t addr)
{
    asm volatile(
        "ldmatrix.sync.aligned.m8n8.x4.shared.b16 {%0,%1,%2,%3}, [%4];"
        : "=r"(r[0]), "=r"(r[1]), "=r"(r[2]), "=r"(r[3])
        : "r"(addr));
}

__global__ __launch_bounds__(256, 2) void gemm_kernel(
    const float* __restrict__ x,
    const float* __restrict__ W0, const float* __restrict__ b0,
    const float* __restrict__ W1, const float* __restrict__ b1,
    const float* __restrict__ att, int N)
{
    extern __shared__ __half smh[];
    __half* xs = smh;                     // [128][HSTRIDE]
    __half* ws = smh + TILE_HALVES;       // [128][HSTRIDE]
    float* rowsum = (float*)(smh + 2 * TILE_HALVES);  // [128]
    float* sbias  = rowsum + 128;                     // [256] (b0|b1)
    float* satt   = sbias + 256;                      // [256]

    const int tid  = threadIdx.x;
    const int row0 = blockIdx.x * 128;

    sbias[tid] = (tid < 128) ? b0[tid] : b1[tid - 128];
    satt[tid]  = att[tid];

    // Stage x tile once (float4 loads -> 2x half2 stores).
    for (int i = tid; i < 128 * 32; i += 256) {
        int r = i >> 5, c4 = (i & 31) * 4;
        int gr = row0 + r;
        float4 xv = (gr < N) ? *(const float4*)(x + (size_t)gr * 128 + c4)
                             : make_float4(0.f, 0.f, 0.f, 0.f);
        *(__half2*)(xs + r * HSTRIDE + c4)     = __floats2half2_rn(xv.x, xv.y);
        *(__half2*)(xs + r * HSTRIDE + c4 + 2) = __floats2half2_rn(xv.z, xv.w);
    }

    const int lane = tid & 31, wid = tid >> 5;
    const int gid  = lane >> 2, tg = lane & 3;
    const int mrow = (wid >> 1) * 32;   // 0,32,64,96
    const int ncol = (wid & 1) * 64;    // 0,64

#pragma unroll
    for (int cb = 0; cb < 2; cb++) {
        const float* W = cb ? W1 : W0;
        for (int i = tid; i < 128 * 32; i += 256) {
            int r = i >> 5, c4 = (i & 31) * 4;
            float4 wv = *(const float4*)(W + r * 128 + c4);
            *(__half2*)(ws + r * HSTRIDE + c4)     = __floats2half2_rn(wv.x, wv.y);
            *(__half2*)(ws + r * HSTRIDE + c4 + 2) = __floats2half2_rn(wv.z, wv.w);
        }
        if (tid < 128) rowsum[tid] = 0.0f;
        __syncthreads();

        uint32_t aAddr0, aAddr1, bAddr[4];
        {
            int rowA = mrow + (lane & 7) + ((lane >> 3) & 1) * 8;
            int kA   = ((lane >> 4) & 1) * 8;
            aAddr0 = (uint32_t)__cvta_generic_to_shared(xs + rowA * HSTRIDE + kA);
            aAddr1 = (uint32_t)__cvta_generic_to_shared(xs + (rowA + 16) * HSTRIDE + kA);
            int nB = (lane & 7) + ((lane >> 4) & 1) * 8;
            int kB = ((lane >> 3) & 1) * 8;
#pragma unroll
            for (int ntp = 0; ntp < 4; ntp++)
                bAddr[ntp] = (uint32_t)__cvta_generic_to_shared(
                    ws + (ncol + ntp * 16 + nB) * HSTRIDE + kB);
        }

        float acc[2][8][4];
#pragma unroll
        for (int mt = 0; mt < 2; mt++)
#pragma unroll
            for (int nt = 0; nt < 8; nt++)
#pragma unroll
                for (int q = 0; q < 4; q++) acc[mt][nt][q] = 0.0f;

#pragma unroll
        for (int ks = 0; ks < 8; ks++) {
            uint32_t a[2][4];
            ldsm_x4(a[0], aAddr0);
            ldsm_x4(a[1], aAddr1);
            uint32_t b[4][4];
#pragma unroll
            for (int ntp = 0; ntp < 4; ntp++)
                ldsm_x4(b[ntp], bAddr[ntp]);

#pragma unroll
            for (int nt = 0; nt < 8; nt++) {
                uint32_t bq0 = b[nt >> 1][(nt & 1) * 2];
                uint32_t bq1 = b[nt >> 1][(nt & 1) * 2 + 1];
#pragma unroll
                for (int mt = 0; mt < 2; mt++)
                    mma_f16(acc[mt][nt], a[mt], bq0, bq1);
            }
            aAddr0 += 32; aAddr1 += 32;
#pragma unroll
            for (int ntp = 0; ntp < 4; ntp++) bAddr[ntp] += 32;
        }

        // Epilogue: bias + relu, store h (fp16 both), attention dots.
        __half* dst = cb ? g_h1h : g_h0h;
        float pr[2][2] = {{0.f, 0.f}, {0.f, 0.f}};
#pragma unroll
        for (int mt = 0; mt < 2; mt++) {
            int rbase = row0 + mrow + mt * 16;
#pragma unroll
            for (int nt = 0; nt < 8; nt++) {
                int n = ncol + nt * 8 + 2 * tg;
                float bia0 = sbias[cb * 128 + n], bia1 = sbias[cb * 128 + n + 1];
                float at0  = satt[cb * 128 + n],  at1  = satt[cb * 128 + n + 1];
                float v00 = fmaxf(acc[mt][nt][0] + bia0, 0.0f);
                float v01 = fmaxf(acc[mt][nt][1] + bia1, 0.0f);
                float v10 = fmaxf(acc[mt][nt][2] + bia0, 0.0f);
                float v11 = fmaxf(acc[mt][nt][3] + bia1, 0.0f);
                int r0r = rbase + gid, r1r = rbase + gid + 8;
                if (r0r < N) *(__half2*)(dst + (size_t)r0r * 128 + n) =
                    __floats2half2_rn(v00, v01);
                if (r1r < N) *(__half2*)(dst + (size_t)r1r * 128 + n) =
                    __floats2half2_rn(v10, v11);
                pr[mt][0] += v00 * at0 + v01 * at1;
                pr[mt][1] += v10 * at0 + v11 * at1;
            }
        }
#pragma unroll
        for (int mt = 0; mt < 2; mt++)
#pragma unroll
            for (int h = 0; h < 2; h++) {
                float p = pr[mt][h];
                p += __shfl_xor_sync(FULL, p, 1);
                p += __shfl_xor_sync(FULL, p, 2);
                pr[mt][h] = p;
            }
        if (tg == 0) {
            atomicAdd(&rowsum[mrow + gid     ], pr[0][0]);
            atomicAdd(&rowsum[mrow + gid + 8 ], pr[0][1]);
            atomicAdd(&rowsum[mrow + gid + 16], pr[1][0]);
            atomicAdd(&rowsum[mrow + gid + 24], pr[1][1]);
        }
        __syncthreads();
        if (tid < 128) {
            int gr = row0 + tid;
            if (gr < N) {
                float p = rowsum[tid];
                p = (p > 0.0f) ? p : 0.2f * p;
                if (cb) g_aneigh[gr] = p;
                else    g_aself[gr]  = p;
            }
        }
        __syncthreads();   // protect ws + rowsum before next pass restages
    }
}

// ---------------------------------------------------------------------------
// Side-stream chain (overlapped with GEMM): zero_deg -> hist -> 3-kernel scan
// ---------------------------------------------------------------------------
__global__ __launch_bounds__(256) void zero_deg_kernel(int N)
{
    int i = blockIdx.x * 256 + threadIdx.x;
    if (i < N + 4) g_deg[i] = 0;
}

__global__ __launch_bounds__(256) void hist_kernel(const int* __restrict__ row, int E)
{
    int i0 = (blockIdx.x * 256 + threadIdx.x) * 4;
    if (i0 + 3 < E) {
        int4 r4 = *(const int4*)(row + i0);
        atomicAdd(&g_deg[r4.x], 1);
        atomicAdd(&g_deg[r4.y], 1);
        atomicAdd(&g_deg[r4.z], 1);
        atomicAdd(&g_deg[r4.w], 1);
    } else {
        for (int i = i0; i < E; i++) atomicAdd(&g_deg[row[i]], 1);
    }
}

__global__ __launch_bounds__(512) void scan1_kernel(int N)
{
    int t = threadIdx.x, b = blockIdx.x;
    int i = b * 512 + t;
    int lane = t & 31, w = t >> 5;
    int v = (i < N) ? g_deg[i] : 0;
#pragma unroll
    for (int o = 1; o < 32; o <<= 1) {
        int n = __shfl_up_sync(FULL, v, o);
        if (lane >= o) v += n;
    }
    __shared__ int ws[16];
    if (lane == 31) ws[w] = v;
    __syncthreads();
    if (w == 0) {
        int s = (lane < 16) ? ws[lane] : 0;
#pragma unroll
        for (int o = 1; o < 16; o <<= 1) {
            int n = __shfl_up_sync(FULL, s, o);
            if (lane >= o) s += n;
        }
        if (lane < 16) ws[lane] = s;
    }
    __syncthreads();
    if (w > 0) v += ws[w - 1];
    if (i < N) g_off[i + 1] = v;
    if (t == 511) g_bsum[b] = v;
}

__global__ __launch_bounds__(512) void scan2_kernel(int nb)
{
    int t = threadIdx.x;
    int lane = t & 31, w = t >> 5;
    int orig = (t < nb) ? g_bsum[t] : 0;
    int v = orig;
#pragma unroll
    for (int o = 1; o < 32; o <<= 1) {
        int n = __shfl_up_sync(FULL, v, o);
        if (lane >= o) v += n;
    }
    __shared__ int ws[16];
    if (lane == 31) ws[w] = v;
    __syncthreads();
    if (w == 0) {
        int s = (lane < 16) ? ws[lane] : 0;
#pragma unroll
        for (int o = 1; o < 16; o <<= 1) {
            int n = __shfl_up_sync(FULL, s, o);
            if (lane >= o) s += n;
        }
        if (lane < 16) ws[lane] = s;
    }
    __syncthreads();
    if (w > 0) v += ws[w - 1];
    if (t < nb) g_boff[t] = v - orig;   // exclusive
}

__global__ __launch_bounds__(512) void scan3_kernel(int N)
{
    int t = threadIdx.x, b = blockIdx.x;
    int i = b * 512 + t;
    if (i < N) {
        int val = g_off[i + 1] + g_boff[b];
        g_off[i + 1] = val;
        g_cur[i] = val - g_deg[i];
    }
    if (i == 0) g_off[0] = 0;
}

// Scatter: 8 edges per thread for deeper load/atomic queues (issue was 4.6%).
__global__ __launch_bounds__(256) void scatter_kernel(
    const int* __restrict__ row, const int* __restrict__ col, int E)
{
    int i0 = (blockIdx.x * 256 + threadIdx.x) * 8;
    if (i0 + 7 < E) {
        int4 ra = *(const int4*)(row + i0);
        int4 rb = *(const int4*)(row + i0 + 4);
        int4 ca = *(const int4*)(col + i0);
        int4 cb = *(const int4*)(col + i0 + 4);
        float a0 = g_aneigh[ca.x], a1 = g_aneigh[ca.y];
        float a2 = g_aneigh[ca.z], a3 = g_aneigh[ca.w];
        float a4 = g_aneigh[cb.x], a5 = g_aneigh[cb.y];
        float a6 = g_aneigh[cb.z], a7 = g_aneigh[cb.w];
        int p0 = atomicAdd(&g_cur[ra.x], 1);
        int p1 = atomicAdd(&g_cur[ra.y], 1);
        int p2 = atomicAdd(&g_cur[ra.z], 1);
        int p3 = atomicAdd(&g_cur[ra.w], 1);
        int p4 = atomicAdd(&g_cur[rb.x], 1);
        int p5 = atomicAdd(&g_cur[rb.y], 1);
        int p6 = atomicAdd(&g_cur[rb.z], 1);
        int p7 = atomicAdd(&g_cur[rb.w], 1);
        g_epack[p0] = make_int2(ca.x, __float_as_int(a0));
        g_epack[p1] = make_int2(ca.y, __float_as_int(a1));
        g_epack[p2] = make_int2(ca.z, __float_as_int(a2));
        g_epack[p3] = make_int2(ca.w, __float_as_int(a3));
        g_epack[p4] = make_int2(cb.x, __float_as_int(a4));
        g_epack[p5] = make_int2(cb.y, __float_as_int(a5));
        g_epack[p6] = make_int2(cb.z, __float_as_int(a6));
        g_epack[p7] = make_int2(cb.w, __float_as_int(a7));
    } else {
        for (int i = i0; i < E; i++) {
            int c = col[i];
            int pos = atomicAdd(&g_cur[row[i]], 1);
            g_epack[pos] = make_int2(c, __float_as_int(g_aneigh[c]));
        }
    }
}

// ---------------------------------------------------------------------------
// Aggregate + fused epilogue: one warp per node (gather, no atomics).
//   agg = sum_{(r,c)} (a_self[r]+a_neigh[c]) * h1[c]   (h1 fp16, e pre-packed)
//   out[r] = norm(h0[r],s0,o0) + norm(agg,s1,o1)       (h0 fp16 stream)
// ---------------------------------------------------------------------------
__global__ __launch_bounds__(256) void agg_kernel(
    const float* __restrict__ scale0, const float* __restrict__ offset0,
    const float* __restrict__ scale1, const float* __restrict__ offset1,
    float* __restrict__ out, int N)
{
    int gw = (blockIdx.x * blockDim.x + threadIdx.x) >> 5;
    int lane = threadIdx.x & 31;
    if (gw >= N) return;

    const int start = g_off[gw];
    const int end   = g_off[gw + 1];
    const float a_r = g_aself[gw];

    float4 acc = make_float4(0.f, 0.f, 0.f, 0.f);

    for (int base = start; base < end; base += 32) {
        int idx = base + lane;
        int2 p = (idx < end) ? g_epack[idx] : make_int2(0, 0);
        int   c = p.x;
        float e = a_r + __int_as_float(p.y);
        int cnt = min(32, end - base);
        int j = 0;
        for (; j + 4 <= cnt; j += 4) {
#pragma unroll
            for (int u = 0; u < 4; u++) {
                int   cj = __shfl_sync(FULL, c, j + u);
                float ej = __shfl_sync(FULL, e, j + u);
                uint2 hp = ((const uint2*)(g_h1h + (size_t)cj * 128))[lane];
                float2 lo = __half22float2(*(__half2*)&hp.x);
                float2 hi = __half22float2(*(__half2*)&hp.y);
                acc.x = fmaf(ej, lo.x, acc.x);
                acc.y = fmaf(ej, lo.y, acc.y);
                acc.z = fmaf(ej, hi.x, acc.z);
                acc.w = fmaf(ej, hi.y, acc.w);
            }
        }
        for (; j < cnt; j++) {
            int   cj = __shfl_sync(FULL, c, j);
            float ej = __shfl_sync(FULL, e, j);
            uint2 hp = ((const uint2*)(g_h1h + (size_t)cj * 128))[lane];
            float2 lo = __half22float2(*(__half2*)&hp.x);
            float2 hi = __half22float2(*(__half2*)&hp.y);
            acc.x = fmaf(ej, lo.x, acc.x);
            acc.y = fmaf(ej, lo.y, acc.y);
            acc.z = fmaf(ej, hi.x, acc.z);
            acc.w = fmaf(ej, hi.y, acc.w);
        }
    }

    // h0 row (fp16 stream -> fp32).
    uint2 h0p = ((const uint2*)(g_h0h + (size_t)gw * 128))[lane];
    float2 h0lo = __half22float2(*(__half2*)&h0p.x);
    float2 h0hi = __half22float2(*(__half2*)&h0p.y);
    float4 h0v = make_float4(h0lo.x, h0lo.y, h0hi.x, h0hi.y);

    float s0 = h0v.x + h0v.y + h0v.z + h0v.w;
    float q0 = h0v.x * h0v.x + h0v.y * h0v.y + h0v.z * h0v.z + h0v.w * h0v.w;
    float s1 = acc.x + acc.y + acc.z + acc.w;
    float q1 = acc.x * acc.x + acc.y * acc.y + acc.z * acc.z + acc.w * acc.w;

#pragma unroll
    for (int o = 16; o > 0; o >>= 1) {
        s0 += __shfl_xor_sync(FULL, s0, o);
        q0 += __shfl_xor_sync(FULL, q0, o);
        s1 += __shfl_xor_sync(FULL, s1, o);
        q1 += __shfl_xor_sync(FULL, q1, o);
    }

    const float m0 = s0 * (1.0f / 128.0f);
    const float i0 = rsqrtf(q0 * (1.0f / 128.0f) - m0 * m0 + 1e-9f);
    const float m1 = s1 * (1.0f / 128.0f);
    const float i1 = rsqrtf(q1 * (1.0f / 128.0f) - m1 * m1 + 1e-9f);

    const float4 sc0 = ((const float4*)scale0)[lane];
    const float4 of0 = ((const float4*)offset0)[lane];
    const float4 sc1 = ((const float4*)scale1)[lane];
    const float4 of1 = ((const float4*)offset1)[lane];

    float4 o4;
    o4.x = (h0v.x - m0) * sc0.x * i0 + of0.x + (acc.x - m1) * sc1.x * i1 + of1.x;
    o4.y = (h0v.y - m0) * sc0.y * i0 + of0.y + (acc.y - m1) * sc1.y * i1 + of1.y;
    o4.z = (h0v.z - m0) * sc0.z * i0 + of0.z + (acc.z - m1) * sc1.z * i1 + of1.z;
    o4.w = (h0v.w - m0) * sc0.w * i0 + of0.w + (acc.w - m1) * sc1.w * i1 + of1.w;
    ((float4*)(out + (size_t)gw * 128))[lane] = o4;
}

// ---------------------------------------------------------------------------
extern "C" void kernel_launch(void* const* d_in, const int* in_sizes, int n_in,
                              void* d_out, int out_size)
{
    const float* x       = (const float*)d_in[0];
    const int*   row     = (const int*)  d_in[1];
    const int*   col     = (const int*)  d_in[2];
    const float* W0      = (const float*)d_in[3];
    const float* b0      = (const float*)d_in[4];
    const float* W1      = (const float*)d_in[5];
    const float* b1      = (const float*)d_in[6];
    const float* att     = (const float*)d_in[7];
    const float* scale0  = (const float*)d_in[8];
    const float* offset0 = (const float*)d_in[9];
    const float* scale1  = (const float*)d_in[10];
    const float* offset1 = (const float*)d_in[11];
    float* out = (float*)d_out;

    const int N = in_sizes[0] / D;
    const int E = in_sizes[1];
    const int nb = (N + 511) / 512;

    // One-time host-side resources (created on the uncaptured correctness call).
    static cudaStream_t s_side = nullptr;
    static cudaEvent_t  s_evFork = nullptr, s_evJoin = nullptr;
    if (!s_side) {
        cudaStreamCreateWithFlags(&s_side, cudaStreamNonBlocking);
        cudaEventCreateWithFlags(&s_evFork, cudaEventDisableTiming);
        cudaEventCreateWithFlags(&s_evJoin, cudaEventDisableTiming);
        cudaFuncSetAttribute(gemm_kernel,
                             cudaFuncAttributeMaxDynamicSharedMemorySize, GEMM_SMEM);
    }

    // Fork: side stream builds the CSR skeleton while stream 0 runs the GEMM.
    cudaEventRecord(s_evFork, 0);
    cudaStreamWaitEvent(s_side, s_evFork, 0);

    zero_deg_kernel<<<(N + 4 + 255) / 256, 256, 0, s_side>>>(N);
    hist_kernel<<<(E / 4 + 255) / 256, 256, 0, s_side>>>(row, E);
    scan1_kernel<<<nb, 512, 0, s_side>>>(N);
    scan2_kernel<<<1, 512, 0, s_side>>>(nb);
    scan3_kernel<<<nb, 512, 0, s_side>>>(N);
    cudaEventRecord(s_evJoin, s_side);

    gemm_kernel<<<(N + 127) / 128, 256, GEMM_SMEM>>>(x, W0, b0, W1, b1, att, N);

    // Join: scatter needs g_aneigh (GEMM) + g_cur (scan).
    cudaStreamWaitEvent(0, s_evJoin, 0);
    scatter_kernel<<<(E / 8 + 255) / 256, 256>>>(row, col, E);
    agg_kernel<<<(N * 32 + 255) / 256, 256>>>(scale0, offset0, scale1, offset1, out, N);
}